// round 12
// baseline (speedup 1.0000x reference)
#include <cuda_runtime.h>

// SSIM loss, fully fused one-kernel version, 4-plane formulation.
// img1, img2: [32,3,512,512] fp32. Output: scalar fp32 = 1 - mean(ssim_map).
//
// Planes: conv(x), conv(y), conv(x^2+y^2), conv(x*y) (x²,y² folded pre-conv).
// Per block: one (plane, 44-row band), 512 threads. Vertical 11-tap conv via
// 11-phase register accumulator ring (1 col/thread), 4-row groups into
// double-buffered smem; horizontal 11-tap conv + SSIM at 4 px/thread (LDS.128).
// Bands 1..10 take a guard-free __noinline__ body (all rows/outputs provably
// in range); bands 0 and 11 take the guarded body. noinline keeps the two
// instantiations' register allocations independent (R10 inlined both into one
// frame -> 128 regs -> spills; this fixes exactly that).

#define HW       512
#define NPLANES  96
#define BAND     44
#define NBANDS   12
#define NBLK     (NBANDS * NPLANES)   // 1152
#define VB       528
#define VB4      (VB / 4)
#define SMEM_DYN (2 * 4 * 4 * VB4 * 16)   // 67584 bytes

namespace {
constexpr double G_[6] = {0.0038659201595884, 0.0285655007845504,
                          0.1353352832366127, 0.4111122905071874,
                          0.8007374029168081, 1.0};
constexpr double GSUM = 2.0*(G_[0]+G_[1]+G_[2]+G_[3]+G_[4]) + 1.0;
constexpr float gwf(int j){ return (float)(G_[j < 6 ? j : 10 - j] / GSUM); }
}

__device__ constexpr float GW[11] = {
    gwf(0), gwf(1), gwf(2), gwf(3), gwf(4), gwf(5),
    gwf(6), gwf(7), gwf(8), gwf(9), gwf(10)};

__device__ float    g_part[NBLK];
__device__ unsigned g_count = 0;

// Deposit j of ingested row (ring phase PH) -> slot (PH+j+6)%11, belonging to
// output row o = r + j - 5. JMIN masks prologue deposits (only o >= o0).
// j == 10 is always the FIRST write to its slot since that slot's emit
// (validated R6/R7: identical rel_err) -> plain MUL, no ring init anywhere.
// Planes: 0 = x, 1 = y, 2 = x^2 + y^2, 3 = x*y.
template<int PH, int JMIN>
__device__ __forceinline__ void ingest(float (&A)[4][11], float v1, float v2)
{
    const float q2  = v1 * v1;
    const float q23 = fmaf(v2, v2, q2);
    const float q4  = v1 * v2;
#pragma unroll
    for (int j = JMIN; j < 11; ++j) {
        const int   s = (PH + j + 6) % 11;
        const float w = GW[j];
        if (j == 10) {
            A[0][s] = w * v1;
            A[1][s] = w * v2;
            A[2][s] = w * q23;
            A[3][s] = w * q4;
        } else {
            A[0][s] = fmaf(w, v1,  A[0][s]);
            A[1][s] = fmaf(w, v2,  A[1][s]);
            A[2][s] = fmaf(w, q23, A[2][s]);
            A[3][s] = fmaf(w, q4,  A[3][s]);
        }
    }
}

// Whole 44-row band. GUARD=false: all row/output indices provably in range
// (bands 1..10: prologue rows >= 39, max ingest row o0+48 <= 488, outputs
// <= 483). GUARD=true: range checks on loads and the output accumulate.
// __noinline__: independent register allocation per instantiation; extern
// shared redeclared inside so staging stays direct LDS addressing.
template<bool GUARD>
__device__ __noinline__ float band_body(
    const float* __restrict__ p1, const float* __restrict__ p2, int o0)
{
    extern __shared__ float4 dynbuf[];   // [2][4][4][VB4]

    const int c  = threadIdx.x;
    const int rr = c >> 7;            // horizontal: row within group
    const int cq = c & 127;           // horizontal: float4 index

    float acc[4][11];   // no init: first touch of every slot is the j==10 MUL
    float nv1[2][4], nv2[2][4];
    float lsum = 0.f;

#define VBUF(B, P, S) ((float*)(dynbuf + (((B)*4 + (P))*4 + (S)) * VB4))
#define GLD(pp, r_) ((!GUARD || (unsigned)(r_) < (unsigned)HW) \
                       ? __ldg(&(pp)[(size_t)(r_) * HW + c]) : 0.f)

    // prefetch banks: bank (G+1)&1 holds ingest rows for group G+1
#define LOADS(G) {                                                          \
        _Pragma("unroll")                                                   \
        for (int i = 0; i < 4; ++i) {                                       \
            const int r_ = o0 + 4 * (G) + 9 + i;                            \
            nv1[((G) + 1) & 1][i] = GLD(p1, r_);                            \
            nv2[((G) + 1) & 1][i] = GLD(p2, r_);                            \
        } }

    // group-0 ingest loads first; the prologue FMA chain hides their latency
    LOADS(-1)

    // ── prologue: rows o0-5 .. o0+4, JMIN = 10-i masking ──
#define PROLOG(i) {                                                         \
        const int r_ = o0 - 5 + (i);                                        \
        const float v1_ = GLD(p1, r_);                                      \
        const float v2_ = GLD(p2, r_);                                      \
        ingest<((i) + 6) % 11, 10 - (i)>(acc, v1_, v2_); }
    PROLOG(0) PROLOG(1) PROLOG(2) PROLOG(3) PROLOG(4)
    PROLOG(5) PROLOG(6) PROLOG(7) PROLOG(8) PROLOG(9)
#undef PROLOG

    // ingest + emit sub-row i of group G: row o0+4G+5+i, slot (4G+i)%11
#define ING(G, i) {                                                         \
        ingest<((4 * (G) + (i)) + 5) % 11, 0>(acc, nv1[(G) & 1][(i)],       \
                                              nv2[(G) & 1][(i)]);           \
        _Pragma("unroll")                                                   \
        for (int p = 0; p < 4; ++p)                                         \
            VBUF((G) & 1, p, (i))[c + 5] = acc[p][(4 * (G) + (i)) % 11]; }

    // horizontal conv + SSIM for group G out of buffer B
#define HSTEP(G, B) {                                                       \
        float hr[4][4];                                                     \
        _Pragma("unroll")                                                   \
        for (int p = 0; p < 4; ++p) {                                       \
            const float4* q = dynbuf + (((B)*4 + p)*4 + rr) * VB4 + cq;     \
            const float4 A = q[0], Bv = q[1], Cv = q[2], D = q[3];          \
            const float v[16] = {A.x, A.y, A.z, A.w,  Bv.x, Bv.y, Bv.z, Bv.w, \
                                 Cv.x, Cv.y, Cv.z, Cv.w,  D.x, D.y, D.z, D.w}; \
            _Pragma("unroll")                                               \
            for (int i = 0; i < 4; ++i) {                                   \
                float s = GW[0] * v[i];                                     \
                _Pragma("unroll")                                           \
                for (int k = 1; k < 11; ++k) s = fmaf(GW[k], v[i + k], s);  \
                hr[p][i] = s;                                               \
            }                                                               \
        }                                                                   \
        if (!GUARD || (o0 + 4 * (G) + rr) < HW) {                           \
            _Pragma("unroll")                                               \
            for (int i = 0; i < 4; ++i) {                                   \
                const float C1 = 1e-4f, C2 = 9e-4f;                         \
                const float m1 = hr[0][i], m2 = hr[1][i];                   \
                const float mu12 = m1 * m2;                                 \
                const float msum = fmaf(m1, m1, m2 * m2);                   \
                const float Anum = 2.f * mu12 + C1;                         \
                const float Bnum = 2.f * (hr[3][i] - mu12) + C2;            \
                const float Cden = msum + C1;                               \
                const float Dden = (hr[2][i] - msum) + C2;                  \
                lsum += __fdividef(Anum * Bnum, Cden * Dden);               \
            }                                                               \
        } }

    // group 0: prefetch group-1 rows, ingest bank 0, emit buf 0
    LOADS(0)
    ING(0, 0) ING(0, 1) ING(0, 2) ING(0, 3)

#define GBODY(G) {                                                          \
        __syncthreads();                                                    \
        if ((G) < 10) { LOADS(G) }                                          \
        HSTEP((G) - 1, ((G) - 1) & 1)                                       \
        ING(G, 0) ING(G, 1) ING(G, 2) ING(G, 3) }
    GBODY(1) GBODY(2) GBODY(3) GBODY(4) GBODY(5)
    GBODY(6) GBODY(7) GBODY(8) GBODY(9) GBODY(10)
#undef GBODY

    __syncthreads();
    HSTEP(10, 0)

#undef HSTEP
#undef ING
#undef LOADS
#undef GLD
#undef VBUF
    return lsum;
}

__global__ __launch_bounds__(512, 1)
void ssim_main(const float* __restrict__ img1, const float* __restrict__ img2,
               float* __restrict__ out)
{
    extern __shared__ float4 dynbuf[];   // [2][4][4][VB4]

    const int c     = threadIdx.x;
    const int band  = blockIdx.x;
    const int plane = blockIdx.y;
    const int o0    = band * BAND;
    const float* __restrict__ p1 = img1 + (size_t)plane * HW * HW;
    const float* __restrict__ p2 = img2 + (size_t)plane * HW * HW;

    __shared__ float  red[16];
    __shared__ double sd[512];
    __shared__ int    amLast;

    // one-time zero of column borders (emits only touch [5,516])
#pragma unroll
    for (int b = 0; b < 2; ++b)
#pragma unroll
        for (int p = 0; p < 4; ++p)
#pragma unroll
            for (int s = 0; s < 4; ++s) {
                float* bb = (float*)(dynbuf + ((b*4 + p)*4 + s) * VB4);
                if (c < 5)    bb[c] = 0.f;
                if (c >= 501) bb[c + 16] = 0.f;   // 517..527
            }

    __syncthreads();

    float lsum;
    if (band == 0 || band == NBANDS - 1)
        lsum = band_body<true >(p1, p2, o0);
    else
        lsum = band_body<false>(p1, p2, o0);

    // ── block reduction ──
    float v = lsum;
#pragma unroll
    for (int off = 16; off; off >>= 1)
        v += __shfl_xor_sync(0xFFFFFFFFu, v, off);
    if ((c & 31) == 0) red[c >> 5] = v;
    __syncthreads();

    if (c == 0) {
        float bs = 0.f;
#pragma unroll
        for (int w = 0; w < 16; ++w) bs += red[w];
        g_part[plane * NBANDS + band] = bs;
        __threadfence();
        const unsigned t = atomicAdd(&g_count, 1u);
        amLast = (t == NBLK - 1);
    }
    __syncthreads();

    if (amLast) {
        __threadfence();
        double s = 0.0;
        for (int i = c; i < NBLK; i += 512) s += (double)g_part[i];
        sd[c] = s;
        __syncthreads();
#pragma unroll
        for (int k = 256; k > 0; k >>= 1) {
            if (c < k) sd[c] += sd[c + k];
            __syncthreads();
        }
        if (c == 0) {
            out[0]  = (float)(1.0 - sd[0] / 25165824.0);  // 32*3*512*512
            g_count = 0;                                   // reset for replay
        }
    }
}

extern "C" void kernel_launch(void* const* d_in, const int* in_sizes, int n_in,
                              void* d_out, int out_size)
{
    (void)in_sizes; (void)n_in; (void)out_size;
    const float* img1 = (const float*)d_in[0];
    const float* img2 = (const float*)d_in[1];
    cudaFuncSetAttribute(ssim_main, cudaFuncAttributeMaxDynamicSharedMemorySize,
                         SMEM_DYN);
    dim3 grid(NBANDS, NPLANES);
    ssim_main<<<grid, 512, SMEM_DYN>>>(img1, img2, (float*)d_out);
}

// round 13
// speedup vs baseline: 1.2145x; 1.2145x over previous
#include <cuda_runtime.h>

// SSIM loss, fully fused one-kernel version, 4-plane formulation.
// img1, img2: [32,3,512,512] fp32. Output: scalar fp32 = 1 - mean(ssim_map).
//
// Planes: conv(x), conv(y), conv(x^2+y^2), conv(x*y) (x²,y² folded pre-conv).
// Per block: one (plane, 44-row band), 512 threads. Vertical 11-tap conv via
// 11-phase register accumulator ring (1 col/thread), 4-row groups into
// double-buffered smem; horizontal 11-tap conv + SSIM at 4 px/thread (LDS.128).
// This is the empirically optimal R7 configuration (150.3 us), with group-0
// ingest loads hoisted above the prologue FMA chain (zero-cost reorder).

#define HW       512
#define NPLANES  96
#define BAND     44
#define NBANDS   12
#define NBLK     (NBANDS * NPLANES)   // 1152
#define VB       528
#define VB4      (VB / 4)
#define SMEM_DYN (2 * 4 * 4 * VB4 * 16)   // 67584 bytes

namespace {
constexpr double G_[6] = {0.0038659201595884, 0.0285655007845504,
                          0.1353352832366127, 0.4111122905071874,
                          0.8007374029168081, 1.0};
constexpr double GSUM = 2.0*(G_[0]+G_[1]+G_[2]+G_[3]+G_[4]) + 1.0;
constexpr float gwf(int j){ return (float)(G_[j < 6 ? j : 10 - j] / GSUM); }
}

__device__ constexpr float GW[11] = {
    gwf(0), gwf(1), gwf(2), gwf(3), gwf(4), gwf(5),
    gwf(6), gwf(7), gwf(8), gwf(9), gwf(10)};

__device__ float    g_part[NBLK];
__device__ unsigned g_count = 0;

// Deposit j of ingested row (ring phase PH) -> slot (PH+j+6)%11, belonging to
// output row o = r + j - 5. JMIN masks prologue deposits (only o >= o0).
// j == 10 is always the FIRST write to its slot since that slot's emit
// (validated R6/R7: identical rel_err) -> plain MUL, no ring init anywhere.
// Planes: 0 = x, 1 = y, 2 = x^2 + y^2, 3 = x*y.
template<int PH, int JMIN>
__device__ __forceinline__ void ingest(float (&A)[4][11], float v1, float v2)
{
    const float q2  = v1 * v1;
    const float q23 = fmaf(v2, v2, q2);
    const float q4  = v1 * v2;
#pragma unroll
    for (int j = JMIN; j < 11; ++j) {
        const int   s = (PH + j + 6) % 11;
        const float w = GW[j];
        if (j == 10) {
            A[0][s] = w * v1;
            A[1][s] = w * v2;
            A[2][s] = w * q23;
            A[3][s] = w * q4;
        } else {
            A[0][s] = fmaf(w, v1,  A[0][s]);
            A[1][s] = fmaf(w, v2,  A[1][s]);
            A[2][s] = fmaf(w, q23, A[2][s]);
            A[3][s] = fmaf(w, q4,  A[3][s]);
        }
    }
}

__global__ __launch_bounds__(512, 1)
void ssim_main(const float* __restrict__ img1, const float* __restrict__ img2,
               float* __restrict__ out)
{
    extern __shared__ float4 dynbuf[];   // [2][4][4][VB4]
#define VBUF(B, P, S) ((float*)(dynbuf + (((B)*4 + (P))*4 + (S)) * VB4))

    const int c     = threadIdx.x;
    const int band  = blockIdx.x;
    const int plane = blockIdx.y;
    const int o0    = band * BAND;
    const float* __restrict__ p1 = img1 + (size_t)plane * HW * HW;
    const float* __restrict__ p2 = img2 + (size_t)plane * HW * HW;

    __shared__ float  red[16];
    __shared__ double sd[512];
    __shared__ int    amLast;

    // one-time zero of column borders (emits only touch [5,516])
#pragma unroll
    for (int b = 0; b < 2; ++b)
#pragma unroll
        for (int p = 0; p < 4; ++p)
#pragma unroll
            for (int s = 0; s < 4; ++s) {
                float* bb = VBUF(b, p, s);
                if (c < 5)    bb[c] = 0.f;
                if (c >= 501) bb[c + 16] = 0.f;   // 517..527
            }

    float acc[4][11];   // no init: first touch of every slot is the j==10 MUL

    __syncthreads();

    // prefetch banks: bank (G+1)&1 holds ingest rows for group G+1
    float nv1[2][4], nv2[2][4];
#define LOADS(G) {                                                           \
        _Pragma("unroll")                                                    \
        for (int i = 0; i < 4; ++i) {                                        \
            const int  r_  = o0 + 4 * (G) + 9 + i;                           \
            const bool ok_ = r_ < HW;                                        \
            nv1[((G) + 1) & 1][i] = ok_ ? __ldg(&p1[(size_t)r_ * HW + c]) : 0.f; \
            nv2[((G) + 1) & 1][i] = ok_ ? __ldg(&p2[(size_t)r_ * HW + c]) : 0.f; \
        } }

    // group-0 ingest loads first; the prologue FMA chain hides their latency
    LOADS(-1)

    // ── prologue: rows o0-5 .. o0+4, JMIN = 10-i masking ──
#define PROLOG(i) {                                                          \
        const int  r_  = o0 - 5 + (i);                                       \
        const bool ok_ = (unsigned)r_ < (unsigned)HW;                        \
        const float v1_ = ok_ ? __ldg(&p1[(size_t)r_ * HW + c]) : 0.f;       \
        const float v2_ = ok_ ? __ldg(&p2[(size_t)r_ * HW + c]) : 0.f;       \
        ingest<((i) + 6) % 11, 10 - (i)>(acc, v1_, v2_); }
    PROLOG(0) PROLOG(1) PROLOG(2) PROLOG(3) PROLOG(4)
    PROLOG(5) PROLOG(6) PROLOG(7) PROLOG(8) PROLOG(9)
#undef PROLOG

    // ingest + emit sub-row i of group G: row o0+4G+5+i, slot (4G+i)%11
#define ING(G, i) {                                                          \
        ingest<((4 * (G) + (i)) + 5) % 11, 0>(acc, nv1[(G) & 1][(i)],        \
                                              nv2[(G) & 1][(i)]);            \
        _Pragma("unroll")                                                    \
        for (int p = 0; p < 4; ++p)                                          \
            VBUF((G) & 1, p, (i))[c + 5] = acc[p][(4 * (G) + (i)) % 11]; }

    float lsum = 0.f;
    const int rr = c >> 7;            // horizontal: row within group
    const int cq = c & 127;           // horizontal: float4 index

    // horizontal conv + SSIM for group G out of buffer B
#define HSTEP(G, B) {                                                        \
        float hr[4][4];                                                      \
        _Pragma("unroll")                                                    \
        for (int p = 0; p < 4; ++p) {                                        \
            const float4* q = dynbuf + (((B)*4 + p)*4 + rr) * VB4 + cq;      \
            const float4 A = q[0], Bv = q[1], Cv = q[2], D = q[3];           \
            const float v[16] = {A.x, A.y, A.z, A.w,  Bv.x, Bv.y, Bv.z, Bv.w,\
                                 Cv.x, Cv.y, Cv.z, Cv.w,  D.x, D.y, D.z, D.w};\
            _Pragma("unroll")                                                \
            for (int i = 0; i < 4; ++i) {                                    \
                float s = GW[0] * v[i];                                      \
                _Pragma("unroll")                                            \
                for (int k = 1; k < 11; ++k) s = fmaf(GW[k], v[i + k], s);   \
                hr[p][i] = s;                                                \
            }                                                                \
        }                                                                    \
        const int o = o0 + 4 * (G) + rr;                                     \
        if (o < HW) {                                                        \
            _Pragma("unroll")                                                \
            for (int i = 0; i < 4; ++i) {                                    \
                const float C1 = 1e-4f, C2 = 9e-4f;                          \
                const float m1 = hr[0][i], m2 = hr[1][i];                    \
                const float mu12 = m1 * m2;                                  \
                const float msum = fmaf(m1, m1, m2 * m2);                    \
                const float Anum = 2.f * mu12 + C1;                          \
                const float Bnum = 2.f * (hr[3][i] - mu12) + C2;             \
                const float Cden = msum + C1;                                \
                const float Dden = (hr[2][i] - msum) + C2;                   \
                lsum += __fdividef(Anum * Bnum, Cden * Dden);                \
            }                                                                \
        } }

    // group 0: prefetch group-1 rows, ingest bank 0, emit buf 0
    LOADS(0)
    ING(0, 0) ING(0, 1) ING(0, 2) ING(0, 3)

#define GBODY(G) {                                                           \
        __syncthreads();                                                     \
        if ((G) < 10) { LOADS(G) }                                           \
        HSTEP((G) - 1, ((G) - 1) & 1)                                        \
        ING(G, 0) ING(G, 1) ING(G, 2) ING(G, 3) }
    GBODY(1) GBODY(2) GBODY(3) GBODY(4) GBODY(5)
    GBODY(6) GBODY(7) GBODY(8) GBODY(9) GBODY(10)
#undef GBODY

    __syncthreads();
    HSTEP(10, 0)

#undef HSTEP
#undef ING
#undef LOADS
#undef VBUF

    // ── block reduction ──
    float v = lsum;
#pragma unroll
    for (int off = 16; off; off >>= 1)
        v += __shfl_xor_sync(0xFFFFFFFFu, v, off);
    if ((c & 31) == 0) red[c >> 5] = v;
    __syncthreads();

    if (c == 0) {
        float bs = 0.f;
#pragma unroll
        for (int w = 0; w < 16; ++w) bs += red[w];
        g_part[plane * NBANDS + band] = bs;
        __threadfence();
        const unsigned t = atomicAdd(&g_count, 1u);
        amLast = (t == NBLK - 1);
    }
    __syncthreads();

    if (amLast) {
        __threadfence();
        double s = 0.0;
        for (int i = c; i < NBLK; i += 512) s += (double)g_part[i];
        sd[c] = s;
        __syncthreads();
#pragma unroll
        for (int k = 256; k > 0; k >>= 1) {
            if (c < k) sd[c] += sd[c + k];
            __syncthreads();
        }
        if (c == 0) {
            out[0]  = (float)(1.0 - sd[0] / 25165824.0);  // 32*3*512*512
            g_count = 0;                                   // reset for replay
        }
    }
}

extern "C" void kernel_launch(void* const* d_in, const int* in_sizes, int n_in,
                              void* d_out, int out_size)
{
    (void)in_sizes; (void)n_in; (void)out_size;
    const float* img1 = (const float*)d_in[0];
    const float* img2 = (const float*)d_in[1];
    cudaFuncSetAttribute(ssim_main, cudaFuncAttributeMaxDynamicSharedMemorySize,
                         SMEM_DYN);
    dim3 grid(NBANDS, NPLANES);
    ssim_main<<<grid, 512, SMEM_DYN>>>(img1, img2, (float*)d_out);
}